// round 15
// baseline (speedup 1.0000x reference)
#include <cuda_runtime.h>
#include <cuda_bf16.h>
#include <cstdint>

#define BMAX    64
#define MA      96
#define NDIM    256
#define EPSF    1e-8f
#define SLAB_F4 2304                 // 96*96/4 float4 per slab
#define NSLABS  (BMAX * MA)          // 6144
#define GRID3   444                  // 3 blocks/SM * 148 SMs = ONE wave

// Scatter buffer for padded node scores [B, MAX_A]. Zero-init at module load;
// invalid positions never written (and paths is 0 there anyway).
__device__ float g_sp[BMAX * MA];
// Handshake counters; reset in-kernel by the last block each launch.
__device__ unsigned g_arrive = 0;
__device__ unsigned g_done   = 0;

__device__ __forceinline__ void cp16(float4* dst_smem, const float4* src_gmem) {
    uint32_t d = (uint32_t)__cvta_generic_to_shared(dst_smem);
    asm volatile("cp.async.cg.shared.global [%0], [%1], 16;\n"
                 :: "r"(d), "l"(src_gmem) : "memory");
}
__device__ __forceinline__ void cp_commit() {
    asm volatile("cp.async.commit_group;\n" ::: "memory");
}
__device__ __forceinline__ void cp_wait1() {
    asm volatile("cp.async.wait_group 1;\n" ::: "memory");
}

// ---------------------------------------------------------------------------
// Single persistent kernel, grid = one full residency wave (444 blocks).
//   Phase 0: commit slab-0 staging (36 KB in flight per block).
//   Phase 1: blocks 0..137 compute 32 distinct node scores each (x read ONCE
//            across the grid — no redundancy), store to g_sp, fence.
//   Barrier: atomic arrive + t0 spin (+ syncthreads). Co-residency guaranteed
//            (grid == wave), so the spin cannot deadlock.
//   Phase 2: measured 5.96 TB/s double-buffered slab loop (unchanged).
//   Tail:    last block resets counters -> graph replays are deterministic.
// ---------------------------------------------------------------------------
extern __shared__ float4 s_dyn[];   // [2][SLAB_F4] slabs, then [24] sp

__global__ __launch_bounds__(256) void fused_path_kernel(
        const float*  __restrict__ x,
        const float*  __restrict__ W,
        const float*  __restrict__ bscal,
        const float4* __restrict__ paths4,
        const int*    __restrict__ pad_idx,
        int total,
        float*        __restrict__ out) {
    float4* buf0 = s_dyn;
    float4* buf1 = s_dyn + SLAB_F4;
    float4* sp_s = s_dyn + 2 * SLAB_F4;   // 24 float4 = 96 floats
    const float4* g_sp4 = reinterpret_cast<const float4*>(g_sp);

    int t  = threadIdx.x;
    int nb = gridDim.x;
    int s0 = blockIdx.x;

    // Stage slab -> buffer with XOR swizzle, 9 cp.async per thread.
    auto stage = [&](int slab, float4* dst) {
        if (slab < NSLABS) {
            const float4* src = paths4 + (size_t)slab * SLAB_F4;
            #pragma unroll
            for (int i = 0; i < 9; i++) {
                int f = t + i * 256;
                int r = f / 24;
                int c = f - r * 24;
                cp16(dst + r * 24 + (c ^ (r & 7)), src + f);
            }
        }
        cp_commit();   // unconditional: keeps group numbering exact
    };

    // Phase 0: slab 0 staging in flight.
    stage(s0, buf0);                       // group 0

    // Phase 1: shared score computation (blocks 0..ceil(total/32)-1).
    // 8 lanes per node, single uniform iteration: all shuffles convergent;
    // inactive lanes clamp the load index and suppress only the store.
    if (blockIdx.x * 32 < total) {
        int sub = t & 7;
        int n   = blockIdx.x * 32 + (t >> 3);
        bool active = n < total;
        int nc  = active ? n : (total - 1);

        const float4* wr = reinterpret_cast<const float4*>(W);
        const float4* xr = reinterpret_cast<const float4*>(x + (size_t)nc * NDIM);
        float s = 0.0f;
        #pragma unroll
        for (int i = 0; i < 8; i++) {
            float4 a  = xr[sub + 8 * i];
            float4 ww = wr[sub + 8 * i];
            s += a.x * ww.x + a.y * ww.y + a.z * ww.z + a.w * ww.w;
        }
        s += __shfl_xor_sync(0xFFFFFFFFu, s, 1);
        s += __shfl_xor_sync(0xFFFFFFFFu, s, 2);
        s += __shfl_xor_sync(0xFFFFFFFFu, s, 4);
        if (active && sub == 0)
            g_sp[pad_idx[n]] = s + bscal[0];
    }
    __threadfence();                       // publish g_sp stores (gpu scope)

    // Grid handshake: arrive, then t0 spins until all 444 blocks arrived.
    if (t == 0) {
        atomicAdd(&g_arrive, 1u);
        while (atomicAdd(&g_arrive, 0u) < (unsigned)GRID3)
            __nanosleep(64);
    }
    __syncthreads();
    __threadfence();                       // acquire: g_sp reads see all stores

    // Phase 2: double-buffered slab loop (measured 5.96 TB/s structure).
    int k = 0;
    for (int s = s0; s < NSLABS; s += nb, k++) {
        if (t < 24) sp_s[t] = g_sp4[(s / MA) * 24 + t];

        float4* cur = (k & 1) ? buf1 : buf0;
        float4* nxt = (k & 1) ? buf0 : buf1;
        stage(s + nb, nxt);

        cp_wait1();              // slab s resident (s+nb may be in flight)
        __syncthreads();

        if (t < 192) {
            int r  = t >> 1;
            int h  = t & 1;
            int sw = r & 7;
            const float4* row = cur + r * 24;
            float num = 0.0f, den = 0.0f;
            #pragma unroll
            for (int j = 0; j < 12; j++) {
                int c = h * 12 + j;
                float4 p  = row[c ^ sw];
                float4 sv = sp_s[c];
                num += p.x * sv.x + p.y * sv.y + p.z * sv.z + p.w * sv.w;
                den += (p.x + p.y) + (p.z + p.w);
            }
            num += __shfl_xor_sync(0xFFFFFFFFu, num, 1);
            den += __shfl_xor_sync(0xFFFFFFFFu, den, 1);
            if (h == 0)
                out[(size_t)s * MA + r] = num / (den + EPSF);
        }
        __syncthreads();         // cur + sp_s free for reuse
    }

    // Tail: last block to finish resets both counters for the next replay.
    if (t == 0) {
        unsigned d = atomicAdd(&g_done, 1u);
        if (d == (unsigned)(GRID3 - 1)) {
            g_arrive = 0;
            g_done   = 0;
            __threadfence();
        }
    }
}

// ---------------------------------------------------------------------------
// Launch. Inputs (metadata order): x, W, b, paths, pad_idx.
// ---------------------------------------------------------------------------
extern "C" void kernel_launch(void* const* d_in, const int* in_sizes, int n_in,
                              void* d_out, int out_size) {
    const float*  x       = (const float*)d_in[0];
    const float*  W       = (const float*)d_in[1];
    const float*  bscal   = (const float*)d_in[2];
    const float4* paths4  = (const float4*)d_in[3];
    const int*    pad_idx = (const int*)d_in[4];
    float*        out     = (float*)d_out;

    int total = in_sizes[4];

    size_t smem = (2 * SLAB_F4 + 24) * sizeof(float4);   // 74112 B
    cudaFuncSetAttribute(fused_path_kernel,
                         cudaFuncAttributeMaxDynamicSharedMemorySize,
                         (int)smem);
    fused_path_kernel<<<GRID3, 256, smem>>>(x, W, bscal, paths4, pad_idx,
                                            total, out);
}